// round 1
// baseline (speedup 1.0000x reference)
#include <cuda_runtime.h>
#include <cuda_bf16.h>
#include <cstdint>

// act_shift = log(1/(1-1e-4) - 1), computed in double then narrowed (matches
// numpy double -> jnp float32 path).
#define ACT_SHIFT (-9.210240366976184)
#define INTERVAL  0.5f

// Scratch: ray start offsets. N is 65536 in the dataset; sized generously.
// (Static __device__ arrays are the allowed scratch mechanism — no cudaMalloc.)
#define MAX_RAYS (1 << 20)
__device__ int g_ray_start[MAX_RAYS + 1];

// ---------------------------------------------------------------------------
// Pass 1: segment boundaries. ray_id is sorted; wherever it increases, record
// the start index for every ray id in the gap (handles empty rays). The last
// element also fills the tail so g_ray_start[N] == M.
// ---------------------------------------------------------------------------
__global__ void find_starts_kernel(const int* __restrict__ ray_id, int M, int Nrays) {
    int i = blockIdx.x * blockDim.x + threadIdx.x;
    if (i >= M) return;
    int cur  = ray_id[i];
    int prev = (i == 0) ? -1 : ray_id[i - 1];   // same cache line as ray_id[i]
    for (int r = prev + 1; r <= cur; ++r) {
        if (r >= 0 && r <= Nrays) g_ray_start[r] = i;
    }
    if (i == M - 1) {
        for (int r = cur + 1; r <= Nrays; ++r) g_ray_start[r] = M;
    }
}

// ---------------------------------------------------------------------------
// Pass 2: one warp per ray. Chunked warp-inclusive scan of sp with a carried
// running sum. weights_i = (1 - exp(-sp_i/2)) * exp(-excl_i/2),
// alphainv_last = exp(-total/2).
// ---------------------------------------------------------------------------
__global__ void ray_scan_kernel(const float* __restrict__ density,
                                float* __restrict__ out_w,
                                float* __restrict__ out_ainv,
                                int Nrays) {
    int warp_id = (int)((blockIdx.x * (unsigned)blockDim.x + threadIdx.x) >> 5);
    int lane    = threadIdx.x & 31;
    if (warp_id >= Nrays) return;

    int start = g_ray_start[warp_id];
    int end   = g_ray_start[warp_id + 1];

    const float shift = (float)ACT_SHIFT;
    float carry = 0.0f;

    for (int base = start; base < end; base += 32) {
        int i = base + lane;
        float sp = 0.0f;
        if (i < end) {
            float x = density[i] + shift;
            // jax.nn.softplus: max(x,0) + log1p(exp(-|x|))  (stable + accurate)
            sp = fmaxf(x, 0.0f) + log1pf(expf(-fabsf(x)));
        }
        // warp inclusive scan of sp
        float v = sp;
        #pragma unroll
        for (int o = 1; o < 32; o <<= 1) {
            float t = __shfl_up_sync(0xFFFFFFFFu, v, o);
            if (lane >= o) v += t;
        }
        float excl = carry + (v - sp);
        if (i < end) {
            // alpha = 1 - exp(-sp*interval), cancellation-free via expm1
            float alpha = -expm1f(-INTERVAL * sp);
            float T     = expf(-INTERVAL * excl);
            out_w[i] = alpha * T;
        }
        carry += __shfl_sync(0xFFFFFFFFu, v, 31);
    }

    if (lane == 0) {
        out_ainv[warp_id] = expf(-INTERVAL * carry);
    }
}

extern "C" void kernel_launch(void* const* d_in, const int* in_sizes, int n_in,
                              void* d_out, int out_size) {
    const float* density = (const float*)d_in[0];
    const int*   ray_id  = (const int*)d_in[1];
    int M = in_sizes[0];
    int Nrays = out_size - M;          // output = [weights(M) | alphainv_last(N)]
    if (Nrays < 0) Nrays = 0;
    if (Nrays > MAX_RAYS) Nrays = MAX_RAYS;

    float* out_w    = (float*)d_out;
    float* out_ainv = (float*)d_out + M;

    {
        int threads = 256;
        int blocks  = (M + threads - 1) / threads;
        find_starts_kernel<<<blocks, threads>>>(ray_id, M, Nrays);
    }
    {
        int threads = 256;                       // 8 warps/block -> 8 rays/block
        long long total_threads = (long long)Nrays * 32;
        int blocks = (int)((total_threads + threads - 1) / threads);
        if (blocks > 0)
            ray_scan_kernel<<<blocks, threads>>>(density, out_w, out_ainv, Nrays);
    }
}

// round 2
// speedup vs baseline: 1.5722x; 1.5722x over previous
#include <cuda_runtime.h>
#include <cuda_bf16.h>
#include <cstdint>

// act_shift = log(1/(1-1e-4) - 1) in double, narrowed (matches numpy path).
#define ACT_SHIFT (-9.210240366976184)
#define INTERVAL  0.5f

#define MAX_RAYS (1 << 20)
__device__ int g_ray_start[MAX_RAYS + 1];

// ---------------------------------------------------------------------------
// softplus(x) = max(x,0) + log1p(e^{-|x|}), fast path: 4-term series (y<1/16
// => |err| ~ y^5/5 < 2e-7). Fallback keeps general-input correctness.
// ---------------------------------------------------------------------------
__device__ __forceinline__ float softplus_f(float x) {
    float ax = fabsf(x);
    float mx = fmaxf(x, 0.0f);
    float y  = __expf(-ax);                       // MUFU EX2 path
    float l;
    if (y < 0.0625f) {
        l = y * (1.0f + y * (-0.5f + y * (0.33333333f + y * (-0.25f))));
    } else {
        l = log1pf(y);                            // rare for this data
    }
    return mx + l;
}

// alpha = -expm1(-sp/2). Fast path: series for u<1/16 (rel err ~ u^4/120).
// Fallback 1-__expf(-u): no cancellation there since alpha > 0.03.
__device__ __forceinline__ float alpha_f(float sp) {
    float u = INTERVAL * sp;
    if (u < 0.0625f) {
        return u * (1.0f + u * (-0.5f + u * (0.16666667f + u * (-0.041666667f))));
    }
    return 1.0f - __expf(-u);
}

// ---------------------------------------------------------------------------
// Pass 1: segment starts, int4-vectorized (4 elements/thread).
// ---------------------------------------------------------------------------
__global__ void find_starts_kernel(const int* __restrict__ ray_id, int M, int Nrays) {
    int t  = blockIdx.x * blockDim.x + threadIdx.x;
    int i0 = t * 4;
    if (i0 >= M) return;

    int c0, c1, c2, c3;
    if (i0 + 3 < M) {
        int4 v = *reinterpret_cast<const int4*>(ray_id + i0);
        c0 = v.x; c1 = v.y; c2 = v.z; c3 = v.w;
    } else {
        c0 = ray_id[i0];
        c1 = (i0 + 1 < M) ? ray_id[i0 + 1] : c0;
        c2 = (i0 + 2 < M) ? ray_id[i0 + 2] : c1;
        c3 = (i0 + 3 < M) ? ray_id[i0 + 3] : c2;
    }
    int prev = (i0 == 0) ? -1 : __ldg(ray_id + i0 - 1);

    int cs[4] = {c0, c1, c2, c3};
    #pragma unroll
    for (int j = 0; j < 4; ++j) {
        int idx = i0 + j;
        if (idx < M) {
            int cur = cs[j];
            for (int r = prev + 1; r <= cur; ++r)
                if (r <= Nrays) g_ray_start[r] = idx;
            prev = cur;
            if (idx == M - 1)
                for (int r = cur + 1; r <= Nrays; ++r) g_ray_start[r] = M;
        }
    }
}

// ---------------------------------------------------------------------------
// Pass 2: one warp per ray, 4 elements per lane per iteration (128/tile).
// Local serial prefix + one warp shfl-scan per tile + sequential carry.
// ---------------------------------------------------------------------------
__global__ void ray_scan_kernel(const float* __restrict__ density,
                                float* __restrict__ out_w,
                                float* __restrict__ out_ainv,
                                int Nrays) {
    int warp_id = (int)((blockIdx.x * (unsigned)blockDim.x + threadIdx.x) >> 5);
    int lane    = threadIdx.x & 31;
    if (warp_id >= Nrays) return;

    int start = g_ray_start[warp_id];
    int end   = g_ray_start[warp_id + 1];

    const float shift = (float)ACT_SHIFT;
    float carry = 0.0f;

    for (int base = start; base < end; base += 128) {
        int i0 = base + lane * 4;

        float sp0 = 0.f, sp1 = 0.f, sp2 = 0.f, sp3 = 0.f;
        if (i0     < end) sp0 = softplus_f(density[i0]     + shift);
        if (i0 + 1 < end) sp1 = softplus_f(density[i0 + 1] + shift);
        if (i0 + 2 < end) sp2 = softplus_f(density[i0 + 2] + shift);
        if (i0 + 3 < end) sp3 = softplus_f(density[i0 + 3] + shift);

        // local inclusive prefix within the lane's 4 items
        float p0 = sp0;
        float p1 = p0 + sp1;
        float p2 = p1 + sp2;
        float p3 = p2 + sp3;

        // warp inclusive scan over lane totals
        float v = p3;
        #pragma unroll
        for (int o = 1; o < 32; o <<= 1) {
            float u = __shfl_up_sync(0xFFFFFFFFu, v, o);
            if (lane >= o) v += u;
        }
        float lane_excl = carry + (v - p3);   // exclusive prefix entering this lane

        if (i0     < end) out_w[i0]     = alpha_f(sp0) * __expf(-INTERVAL * lane_excl);
        if (i0 + 1 < end) out_w[i0 + 1] = alpha_f(sp1) * __expf(-INTERVAL * (lane_excl + p0));
        if (i0 + 2 < end) out_w[i0 + 2] = alpha_f(sp2) * __expf(-INTERVAL * (lane_excl + p1));
        if (i0 + 3 < end) out_w[i0 + 3] = alpha_f(sp3) * __expf(-INTERVAL * (lane_excl + p2));

        carry += __shfl_sync(0xFFFFFFFFu, v, 31);  // tile total
    }

    if (lane == 0) {
        out_ainv[warp_id] = __expf(-INTERVAL * carry);
    }
}

extern "C" void kernel_launch(void* const* d_in, const int* in_sizes, int n_in,
                              void* d_out, int out_size) {
    const float* density = (const float*)d_in[0];
    const int*   ray_id  = (const int*)d_in[1];
    int M = in_sizes[0];
    int Nrays = out_size - M;            // output = [weights(M) | alphainv_last(N)]
    if (Nrays < 0) Nrays = 0;
    if (Nrays > MAX_RAYS) Nrays = MAX_RAYS;

    float* out_w    = (float*)d_out;
    float* out_ainv = (float*)d_out + M;

    {
        int threads = 256;
        int quads   = (M + 3) / 4;
        int blocks  = (quads + threads - 1) / threads;
        find_starts_kernel<<<blocks, threads>>>(ray_id, M, Nrays);
    }
    {
        int threads = 256;                       // 8 warps/block -> 8 rays/block
        long long total_threads = (long long)Nrays * 32;
        int blocks = (int)((total_threads + threads - 1) / threads);
        if (blocks > 0)
            ray_scan_kernel<<<blocks, threads>>>(density, out_w, out_ainv, Nrays);
    }
}

// round 3
// speedup vs baseline: 1.6032x; 1.0197x over previous
#include <cuda_runtime.h>
#include <cuda_bf16.h>
#include <cstdint>

// act_shift = log(1/(1-1e-4) - 1) in double, narrowed (matches numpy path).
#define ACT_SHIFT (-9.210240366976184)
#define INTERVAL  0.5f

#define MAX_RAYS (1 << 20)
__device__ int g_ray_start[MAX_RAYS + 1];

// ---------------------------------------------------------------------------
// softplus(x) = max(x,0) + log1p(e^{-|x|}); fast series for y < 1/16
// (|err| ~ y^5/5 < 2e-7), libm fallback keeps general-input correctness.
// ---------------------------------------------------------------------------
__device__ __forceinline__ float softplus_f(float x) {
    float ax = fabsf(x);
    float mx = fmaxf(x, 0.0f);
    float y  = __expf(-ax);                       // MUFU EX2 path
    float l;
    if (y < 0.0625f) {
        l = y * (1.0f + y * (-0.5f + y * (0.33333333f + y * (-0.25f))));
    } else {
        l = log1pf(y);                            // ~never for this data
    }
    return mx + l;
}

// alpha = -expm1(-sp/2): series for u < 1/16 (rel err ~ u^4/120), else 1-exp.
__device__ __forceinline__ float alpha_f(float sp) {
    float u = INTERVAL * sp;
    if (u < 0.0625f) {
        return u * (1.0f + u * (-0.5f + u * (0.16666667f + u * (-0.041666667f))));
    }
    return 1.0f - __expf(-u);
}

// ---------------------------------------------------------------------------
// Pass 1: segment starts. 8 elements (two int4) per thread for MLP.
// ---------------------------------------------------------------------------
__global__ void find_starts_kernel(const int* __restrict__ ray_id, int M, int Nrays) {
    int t  = blockIdx.x * blockDim.x + threadIdx.x;
    int i0 = t * 8;
    if (i0 >= M) return;

    int c[8];
    if (i0 + 7 < M) {
        int4 a = *reinterpret_cast<const int4*>(ray_id + i0);
        int4 b = *reinterpret_cast<const int4*>(ray_id + i0 + 4);
        c[0]=a.x; c[1]=a.y; c[2]=a.z; c[3]=a.w;
        c[4]=b.x; c[5]=b.y; c[6]=b.z; c[7]=b.w;
    } else {
        int last = ray_id[i0];
        #pragma unroll
        for (int j = 0; j < 8; ++j) {
            if (i0 + j < M) last = ray_id[i0 + j];
            c[j] = last;
        }
    }
    int prev = (i0 == 0) ? -1 : __ldg(ray_id + i0 - 1);

    #pragma unroll
    for (int j = 0; j < 8; ++j) {
        int idx = i0 + j;
        if (idx < M) {
            int cur = c[j];
            for (int r = prev + 1; r <= cur; ++r)
                if (r <= Nrays) g_ray_start[r] = idx;
            prev = cur;
            if (idx == M - 1)
                for (int r = cur + 1; r <= Nrays; ++r) g_ray_start[r] = M;
        }
    }
}

// ---------------------------------------------------------------------------
// Pass 2: one warp per ray. Tiles aligned to 4-element boundaries so loads
// and stores are LDG.128/STG.128. Out-of-segment slots contribute sp=0 and
// are never stored (another ray's warp owns them).
// Transmittance chained: T_{j+1} = T_j * (1 - alpha_j)  (exact identity),
// so only ONE __expf per lane per tile.
// ---------------------------------------------------------------------------
__global__ void ray_scan_kernel(const float* __restrict__ density,
                                float* __restrict__ out_w,
                                float* __restrict__ out_ainv,
                                int Nrays, int M) {
    int warp_id = (int)((blockIdx.x * (unsigned)blockDim.x + threadIdx.x) >> 5);
    int lane    = threadIdx.x & 31;
    if (warp_id >= Nrays) return;

    int start = g_ray_start[warp_id];
    int end   = g_ray_start[warp_id + 1];

    const float shift = (float)ACT_SHIFT;
    float carry = 0.0f;

    for (int abase = (start & ~3); abase < end; abase += 128) {
        int i0 = abase + lane * 4;

        float d0 = 0.f, d1 = 0.f, d2 = 0.f, d3 = 0.f;
        if (i0 + 3 < M) {
            float4 v = *reinterpret_cast<const float4*>(density + i0);
            d0 = v.x; d1 = v.y; d2 = v.z; d3 = v.w;
        } else {
            if (i0     < M) d0 = density[i0];
            if (i0 + 1 < M) d1 = density[i0 + 1];
            if (i0 + 2 < M) d2 = density[i0 + 2];
            if (i0 + 3 < M) d3 = density[i0 + 3];
        }

        bool v0 = (i0     >= start) && (i0     < end);
        bool v1 = (i0 + 1 >= start) && (i0 + 1 < end);
        bool v2 = (i0 + 2 >= start) && (i0 + 2 < end);
        bool v3 = (i0 + 3 >= start) && (i0 + 3 < end);

        float sp0 = v0 ? softplus_f(d0 + shift) : 0.0f;
        float sp1 = v1 ? softplus_f(d1 + shift) : 0.0f;
        float sp2 = v2 ? softplus_f(d2 + shift) : 0.0f;
        float sp3 = v3 ? softplus_f(d3 + shift) : 0.0f;

        // local inclusive prefix
        float p0 = sp0;
        float p1 = p0 + sp1;
        float p2 = p1 + sp2;
        float p3 = p2 + sp3;

        // warp inclusive scan over lane totals
        float v = p3;
        #pragma unroll
        for (int o = 1; o < 32; o <<= 1) {
            float u = __shfl_up_sync(0xFFFFFFFFu, v, o);
            if (lane >= o) v += u;
        }
        float lane_excl = carry + (v - p3);

        // transmittance entering this lane, then chain through 4 elements
        float T  = __expf(-INTERVAL * lane_excl);
        float a0 = alpha_f(sp0);  float w0 = a0 * T;  T *= (1.0f - a0);
        float a1 = alpha_f(sp1);  float w1 = a1 * T;  T *= (1.0f - a1);
        float a2 = alpha_f(sp2);  float w2 = a2 * T;  T *= (1.0f - a2);
        float a3 = alpha_f(sp3);  float w3 = a3 * T;

        if (v0 && v3 && (i0 + 3 < M)) {
            *reinterpret_cast<float4*>(out_w + i0) = make_float4(w0, w1, w2, w3);
        } else {
            if (v0) out_w[i0]     = w0;
            if (v1) out_w[i0 + 1] = w1;
            if (v2) out_w[i0 + 2] = w2;
            if (v3) out_w[i0 + 3] = w3;
        }

        carry += __shfl_sync(0xFFFFFFFFu, v, 31);
    }

    if (lane == 0) {
        out_ainv[warp_id] = __expf(-INTERVAL * carry);
    }
}

extern "C" void kernel_launch(void* const* d_in, const int* in_sizes, int n_in,
                              void* d_out, int out_size) {
    const float* density = (const float*)d_in[0];
    const int*   ray_id  = (const int*)d_in[1];
    int M = in_sizes[0];
    int Nrays = out_size - M;            // output = [weights(M) | alphainv_last(N)]
    if (Nrays < 0) Nrays = 0;
    if (Nrays > MAX_RAYS) Nrays = MAX_RAYS;

    float* out_w    = (float*)d_out;
    float* out_ainv = (float*)d_out + M;

    {
        int threads = 256;
        int octs    = (M + 7) / 8;
        int blocks  = (octs + threads - 1) / threads;
        find_starts_kernel<<<blocks, threads>>>(ray_id, M, Nrays);
    }
    {
        int threads = 256;                       // 8 warps/block -> 8 rays/block
        long long total_threads = (long long)Nrays * 32;
        int blocks = (int)((total_threads + threads - 1) / threads);
        if (blocks > 0)
            ray_scan_kernel<<<blocks, threads>>>(density, out_w, out_ainv, Nrays, M);
    }
}

// round 4
// speedup vs baseline: 1.8326x; 1.1431x over previous
#include <cuda_runtime.h>
#include <cuda_bf16.h>
#include <cstdint>

// act_shift = log(1/(1-1e-4) - 1) in double, narrowed (matches numpy path).
#define ACT_SHIFT (-9.210240366976184)
#define LOG2E_D   (1.4426950408889634)

#define MAX_RAYS (1 << 20)
__device__ int g_ray_start[MAX_RAYS + 1];

// ---------------------------------------------------------------------------
// Pass 1: segment starts. 16 elements (four int4) per thread for MLP.
// ---------------------------------------------------------------------------
__global__ void find_starts_kernel(const int* __restrict__ ray_id, int M, int Nrays) {
    int t  = blockIdx.x * blockDim.x + threadIdx.x;
    int i0 = t * 16;
    if (i0 >= M) return;

    int c[16];
    if (i0 + 15 < M) {
        int4 a = *reinterpret_cast<const int4*>(ray_id + i0);
        int4 b = *reinterpret_cast<const int4*>(ray_id + i0 + 4);
        int4 e = *reinterpret_cast<const int4*>(ray_id + i0 + 8);
        int4 f = *reinterpret_cast<const int4*>(ray_id + i0 + 12);
        c[0]=a.x; c[1]=a.y; c[2]=a.z; c[3]=a.w;
        c[4]=b.x; c[5]=b.y; c[6]=b.z; c[7]=b.w;
        c[8]=e.x; c[9]=e.y; c[10]=e.z; c[11]=e.w;
        c[12]=f.x; c[13]=f.y; c[14]=f.z; c[15]=f.w;
    } else {
        int last = ray_id[i0];
        #pragma unroll
        for (int j = 0; j < 16; ++j) {
            if (i0 + j < M) last = ray_id[i0 + j];
            c[j] = last;
        }
    }
    int prev = (i0 == 0) ? -1 : __ldg(ray_id + i0 - 1);   // L1 hit (neighbor's line)

    #pragma unroll
    for (int j = 0; j < 16; ++j) {
        int idx = i0 + j;
        if (idx < M) {
            int cur = c[j];
            if (cur != prev) {                    // rare
                for (int r = prev + 1; r <= cur; ++r)
                    if (r <= Nrays) g_ray_start[r] = idx;
            }
            prev = cur;
            if (idx == M - 1)
                for (int r = cur + 1; r <= Nrays; ++r) g_ray_start[r] = M;
        }
    }
}

// ---------------------------------------------------------------------------
// Pass 2: one warp per ray, product-domain segmented scan.
//   y = e^{d+shift},  q = 1+y   (softplus = log q exactly, for all x)
//   T_i = (prod_{j<i} q_j)^{-1/2}          -> warp product scan + rsqrtf
//   alpha = 1-(1+y)^{-1/2} = y*poly(y)     -> pure FMA, no MUFU
//   alphainv_last = (prod q)^{-1/2}
// One EX2 per element + one RSQ per lane-tile: ~1.05 MUFU/elem.
// ---------------------------------------------------------------------------
__global__ void __launch_bounds__(256)
ray_scan_kernel(const float* __restrict__ density,
                float* __restrict__ out_w,
                float* __restrict__ out_ainv,
                int Nrays, int M) {
    int warp_id = (int)((blockIdx.x * (unsigned)blockDim.x + threadIdx.x) >> 5);
    int lane    = threadIdx.x & 31;
    if (warp_id >= Nrays) return;

    int start = g_ray_start[warp_id];
    int end   = g_ray_start[warp_id + 1];

    const float l2e  = (float)LOG2E_D;
    const float sl2e = (float)(ACT_SHIFT * LOG2E_D);

    float carry = 1.0f;                           // running product of q

    for (int abase = (start & ~3); abase < end; abase += 128) {
        int i0 = abase + lane * 4;

        float d0 = 0.f, d1 = 0.f, d2 = 0.f, d3 = 0.f;
        if (i0 + 3 < M) {
            float4 v4 = *reinterpret_cast<const float4*>(density + i0);
            d0 = v4.x; d1 = v4.y; d2 = v4.z; d3 = v4.w;
        } else {
            if (i0     < M) d0 = density[i0];
            if (i0 + 1 < M) d1 = density[i0 + 1];
            if (i0 + 2 < M) d2 = density[i0 + 2];
            if (i0 + 3 < M) d3 = density[i0 + 3];
        }

        bool v0 = (i0     >= start) && (i0     < end);
        bool v1 = (i0 + 1 >= start) && (i0 + 1 < end);
        bool v2 = (i0 + 2 >= start) && (i0 + 2 < end);
        bool v3 = (i0 + 3 >= start) && (i0 + 3 < end);

        float y0 = v0 ? exp2f(fmaf(d0, l2e, sl2e)) : 0.0f;
        float y1 = v1 ? exp2f(fmaf(d1, l2e, sl2e)) : 0.0f;
        float y2 = v2 ? exp2f(fmaf(d2, l2e, sl2e)) : 0.0f;
        float y3 = v3 ? exp2f(fmaf(d3, l2e, sl2e)) : 0.0f;

        float q0 = 1.0f + y0, q1 = 1.0f + y1, q2 = 1.0f + y2, q3 = 1.0f + y3;

        // local prefix products
        float P0 = q0;
        float P1 = P0 * q1;
        float P2 = P1 * q2;
        float P3 = P2 * q3;

        // warp inclusive product scan of lane totals
        float v = P3;
        #pragma unroll
        for (int o = 1; o < 32; o <<= 1) {
            float u = __shfl_up_sync(0xFFFFFFFFu, v, o);
            if (lane >= o) v *= u;
        }
        // exclusive product entering this lane
        float ve = __shfl_up_sync(0xFFFFFFFFu, v, 1);
        if (lane == 0) ve = 1.0f;

        float T = rsqrtf(carry * ve);             // transmittance entering lane

        // alpha = y*(1/2 - 3/8 y + 5/16 y^2 - 35/128 y^3), valid y < 1/16
        float a0 = y0 * fmaf(y0, fmaf(y0, fmaf(y0, -0.2734375f, 0.3125f), -0.375f), 0.5f);
        float a1 = y1 * fmaf(y1, fmaf(y1, fmaf(y1, -0.2734375f, 0.3125f), -0.375f), 0.5f);
        float a2 = y2 * fmaf(y2, fmaf(y2, fmaf(y2, -0.2734375f, 0.3125f), -0.375f), 0.5f);
        float a3 = y3 * fmaf(y3, fmaf(y3, fmaf(y3, -0.2734375f, 0.3125f), -0.375f), 0.5f);

        // rare slow path (big y): exact alpha = 1 - (1+y)^{-1/2}
        float ymax = fmaxf(fmaxf(y0, y1), fmaxf(y2, y3));
        if (__any_sync(0xFFFFFFFFu, !(ymax < 0.0625f))) {
            if (!(y0 < 0.0625f)) a0 = 1.0f - rsqrtf(q0);
            if (!(y1 < 0.0625f)) a1 = 1.0f - rsqrtf(q1);
            if (!(y2 < 0.0625f)) a2 = 1.0f - rsqrtf(q2);
            if (!(y3 < 0.0625f)) a3 = 1.0f - rsqrtf(q3);
        }

        // chain transmittance exactly: T *= (1 - alpha)
        float w0 = a0 * T;  T *= (1.0f - a0);
        float w1 = a1 * T;  T *= (1.0f - a1);
        float w2 = a2 * T;  T *= (1.0f - a2);
        float w3 = a3 * T;

        if (v0 && v3 && (i0 + 3 < M)) {
            *reinterpret_cast<float4*>(out_w + i0) = make_float4(w0, w1, w2, w3);
        } else {
            if (v0) out_w[i0]     = w0;
            if (v1) out_w[i0 + 1] = w1;
            if (v2) out_w[i0 + 2] = w2;
            if (v3) out_w[i0 + 3] = w3;
        }

        carry *= __shfl_sync(0xFFFFFFFFu, v, 31);
    }

    if (lane == 0) {
        out_ainv[warp_id] = rsqrtf(carry);
    }
}

extern "C" void kernel_launch(void* const* d_in, const int* in_sizes, int n_in,
                              void* d_out, int out_size) {
    const float* density = (const float*)d_in[0];
    const int*   ray_id  = (const int*)d_in[1];
    int M = in_sizes[0];
    int Nrays = out_size - M;            // output = [weights(M) | alphainv_last(N)]
    if (Nrays < 0) Nrays = 0;
    if (Nrays > MAX_RAYS) Nrays = MAX_RAYS;

    float* out_w    = (float*)d_out;
    float* out_ainv = (float*)d_out + M;

    {
        int threads = 256;
        int chunks  = (M + 15) / 16;
        int blocks  = (chunks + threads - 1) / threads;
        find_starts_kernel<<<blocks, threads>>>(ray_id, M, Nrays);
    }
    {
        int threads = 256;                       // 8 warps/block -> 8 rays/block
        long long total_threads = (long long)Nrays * 32;
        int blocks = (int)((total_threads + threads - 1) / threads);
        if (blocks > 0)
            ray_scan_kernel<<<blocks, threads>>>(density, out_w, out_ainv, Nrays, M);
    }
}